// round 8
// baseline (speedup 1.0000x reference)
#include <cuda_runtime.h>
#include <math.h>

#define BB 2048
#define CC 3
#define TT 300
#define JJ 25
#define TJ (TT * JJ)            // 7500 elements per (b,c) slice
#define NSLICE (BB * CC)        // 6144 slices
#define WPB 8                   // warps per block (1 warp = 1 slice)
#define NBLK (NSLICE / WPB)     // 768 blocks
#define NTHREADS (WPB * 32)
#define NF4 (TJ / 4)            // 1875 float4 per slice
#define KMAX (NF4 / JJ)         // 75 groups of 25 float4 (= 4 frames each)

// Global accumulators (allocation-free scratch). Zero-initialized at load;
// last finishing block resets them -> deterministic across graph replays.
__device__ double g_rec = 0.0;
__device__ double g_smooth = 0.0;
__device__ unsigned int g_count = 0u;

// Element (lane,kk) in group k: j = (4*lane+kk) % 25, invariant over k.
// Interior contribution to (sx - st): d - d*(x+t), d = x-t.
// FIRST (t==0 rows, 4l+kk<25): only +d.   LAST (t==299, 4l+kk>=75): only -d*(x+t).
template <bool FIRST, bool LAST>
__device__ __forceinline__ void process4(float4 xv, float4 tv, int fourl,
                                         float acc[4], float& rec) {
    const float xa[4] = {xv.x, xv.y, xv.z, xv.w};
    const float ta[4] = {tv.x, tv.y, tv.z, tv.w};
    #pragma unroll
    for (int kk = 0; kk < 4; kk++) {
        const float d  = xa[kk] - ta[kk];
        rec = fmaf(d, d, rec);
        const float xt = xa[kk] + ta[kk];
        float c;
        if (FIRST) {
            c = d;
            if (fourl + kk >= 25) c = fmaf(-d, xt, c);
        } else if (LAST) {
            c = (fourl + kk < 75) ? d : 0.0f;
            c = fmaf(-d, xt, c);
        } else {
            c = fmaf(-d, xt, d);
        }
        acc[kk] += c;
    }
}

__global__ void __launch_bounds__(NTHREADS)
loss_kernel(const float* __restrict__ x, const float* __restrict__ tg,
            float* __restrict__ out) {
    const int warp = threadIdx.x >> 5;
    const int lane = threadIdx.x & 31;
    const int slice = blockIdx.x * WPB + warp;          // < 6144

    const float4* __restrict__ x4 = (const float4*)(x  + (size_t)slice * TJ);
    const float4* __restrict__ t4 = (const float4*)(tg + (size_t)slice * TJ);

    const bool active = (lane < JJ);
    const int fourl = lane * 4;
    // Inactive lanes read the slice base: in-bounds, broadcast, no extra lines.
    const int ld = active ? lane : 0;

    float acc[4] = {0.0f, 0.0f, 0.0f, 0.0f};
    float rec = 0.0f;

    // Front-batch: loads for k=0 plus pipeline slots for k=1,2 (6 LDG.128).
    float4 x0 = __ldg(x4 + ld);
    float4 t0 = __ldg(t4 + ld);
    float4 px0 = __ldg(x4 + 1 * JJ + ld);
    float4 pt0 = __ldg(t4 + 1 * JJ + ld);
    float4 px1 = __ldg(x4 + 2 * JJ + ld);
    float4 pt1 = __ldg(t4 + 2 * JJ + ld);

    if (!active) { x0 = {0,0,0,0}; t0 = {0,0,0,0}; }
    process4<true, false>(x0, t0, fourl, acc, rec);

    // Interior k = 1..73 (73 iterations), depth-2 pipeline: load k+2.
    #pragma unroll 2
    for (int k = 1; k < KMAX - 1; k++) {
        float4 xv, tv;
        if ((k & 1) == 1) { xv = px0; tv = pt0; } else { xv = px1; tv = pt1; }
        const int kn = k + 2;
        if (kn <= KMAX - 1) {
            float4 nx = __ldg(x4 + kn * JJ + ld);
            float4 nt = __ldg(t4 + kn * JJ + ld);
            if ((k & 1) == 1) { px0 = nx; pt0 = nt; } else { px1 = nx; pt1 = nt; }
        }
        if (!active) { xv = {0,0,0,0}; tv = {0,0,0,0}; }
        process4<false, false>(xv, tv, fourl, acc, rec);
    }
    // k = 74 (LAST): sits in the slot of parity (74-1)&1 = 1 -> px1/pt1.
    {
        float4 xv = px1, tv = pt1;
        if (!active) { xv = {0,0,0,0}; tv = {0,0,0,0}; }
        process4<false, true>(xv, tv, fourl, acc, rec);
    }

    // rec: full-warp shuffle reduce.
    #pragma unroll
    for (int o = 16; o > 0; o >>= 1)
        rec += __shfl_xor_sync(0xffffffffu, rec, o);

    // Smooth: fold 100 (lane,kk) accumulators into per-joint sums via smem.
    __shared__ float sj[WPB][JJ];
    if (active) sj[warp][lane] = 0.0f;
    __syncwarp();
    if (active) {
        #pragma unroll
        for (int kk = 0; kk < 4; kk++) {
            const int v = fourl + kk;
            const int j = (v >= 75) ? v - 75 : (v >= 50) ? v - 50
                        : (v >= 25) ? v - 25 : v;
            atomicAdd(&sj[warp][j], acc[kk]);
        }
    }
    __syncwarp();

    float av = (lane < JJ - 1) ? fabsf(sj[warp][lane]) : 0.0f;
    #pragma unroll
    for (int o = 16; o > 0; o >>= 1)
        av += __shfl_xor_sync(0xffffffffu, av, o);

    __shared__ double s_rec[WPB];
    __shared__ double s_sm[WPB];
    if (lane == 0) {
        s_rec[warp] = (double)rec;
        s_sm[warp]  = sqrt((double)av) / (double)TJ;
    }
    __syncthreads();

    if (threadIdx.x == 0) {
        double rtot = 0.0, stot = 0.0;
        #pragma unroll
        for (int w = 0; w < WPB; w++) { rtot += s_rec[w]; stot += s_sm[w]; }
        atomicAdd(&g_rec, rtot);
        atomicAdd(&g_smooth, stot);
        __threadfence();
        const unsigned int ticket = atomicAdd(&g_count, 1u);
        if (ticket == NBLK - 1) {
            const double rec_sum = atomicAdd(&g_rec, 0.0);
            const double sm_sum  = atomicAdd(&g_smooth, 0.0);
            const double rec_mean    = rec_sum / ((double)BB * CC * TT * JJ);
            const double smooth_mean = sm_sum  / ((double)BB * CC);
            out[0] = (float)(2.0 * rec_mean + 3.0 * smooth_mean);
            g_rec = 0.0;
            g_smooth = 0.0;
            __threadfence();
            g_count = 0u;
        }
    }
}

extern "C" void kernel_launch(void* const* d_in, const int* in_sizes, int n_in,
                              void* d_out, int out_size) {
    const float* x  = (const float*)d_in[0];
    const float* tg = (const float*)d_in[1];
    float* out = (float*)d_out;

    loss_kernel<<<NBLK, NTHREADS>>>(x, tg, out);
}

// round 10
// speedup vs baseline: 1.1835x; 1.1835x over previous
#include <cuda_runtime.h>
#include <math.h>

#define BB 2048
#define CC 3
#define TT 300
#define JJ 25
#define TJ (TT * JJ)            // 7500 elements per (b,c) slice
#define NSLICE (BB * CC)        // 6144 slices
#define WPB 2                   // warps per block (1 warp = 1 slice)
#define NBLK (NSLICE / WPB)     // 3072 blocks -> fine-grained SM balancing
#define NTHREADS (WPB * 32)
#define NF4 (TJ / 4)            // 1875 float4 per slice
#define KMAX (NF4 / JJ)         // 75 groups of 25 float4 (= 4 frames each)

// Global accumulators (allocation-free scratch). Zero-initialized at load;
// last finishing block resets them -> deterministic across graph replays.
__device__ double g_rec = 0.0;
__device__ double g_smooth = 0.0;
__device__ unsigned int g_count = 0u;

// Element (lane,kk) in group k: j = (4*lane+kk) % 25, invariant over k.
// Interior contribution to (sx - st): d - d*(x+t), d = x-t.
// FIRST (t==0 rows, 4l+kk<25): only +d.   LAST (t==299, 4l+kk>=75): only -d*(x+t).
template <bool FIRST, bool LAST>
__device__ __forceinline__ void process4(float4 xv, float4 tv, int fourl,
                                         float acc[4], float& rec) {
    const float xa[4] = {xv.x, xv.y, xv.z, xv.w};
    const float ta[4] = {tv.x, tv.y, tv.z, tv.w};
    #pragma unroll
    for (int kk = 0; kk < 4; kk++) {
        const float d  = xa[kk] - ta[kk];
        rec = fmaf(d, d, rec);
        const float xt = xa[kk] + ta[kk];
        float c;
        if (FIRST) {
            c = d;
            if (fourl + kk >= 25) c = fmaf(-d, xt, c);
        } else if (LAST) {
            c = (fourl + kk < 75) ? d : 0.0f;
            c = fmaf(-d, xt, c);
        } else {
            c = fmaf(-d, xt, d);
        }
        acc[kk] += c;
    }
}

__global__ void __launch_bounds__(NTHREADS)
loss_kernel(const float* __restrict__ x, const float* __restrict__ tg,
            float* __restrict__ out) {
    const int warp = threadIdx.x >> 5;
    const int lane = threadIdx.x & 31;
    const int slice = blockIdx.x * WPB + warp;          // < 6144

    const float4* __restrict__ x4 = (const float4*)(x  + (size_t)slice * TJ);
    const float4* __restrict__ t4 = (const float4*)(tg + (size_t)slice * TJ);

    const bool active = (lane < JJ);
    const int fourl = lane * 4;

    float acc[4] = {0.0f, 0.0f, 0.0f, 0.0f};
    float rec = 0.0f;

    const float4 z4 = {0.0f, 0.0f, 0.0f, 0.0f};

    // k = 0 (contains all t==0 elements)
    {
        float4 xv = active ? __ldg(x4 + lane) : z4;
        float4 tv = active ? __ldg(t4 + lane) : z4;
        process4<true, false>(xv, tv, fourl, acc, rec);
    }
    // interior groups: t in (0, 299) for every element -> branchless
    #pragma unroll 2
    for (int k = 1; k < KMAX - 1; k++) {
        float4 xv = active ? __ldg(x4 + k * JJ + lane) : z4;
        float4 tv = active ? __ldg(t4 + k * JJ + lane) : z4;
        process4<false, false>(xv, tv, fourl, acc, rec);
    }
    // k = 74 (contains all t==299 elements)
    {
        float4 xv = active ? __ldg(x4 + (KMAX - 1) * JJ + lane) : z4;
        float4 tv = active ? __ldg(t4 + (KMAX - 1) * JJ + lane) : z4;
        process4<false, true>(xv, tv, fourl, acc, rec);
    }

    // rec: full-warp shuffle reduce.
    #pragma unroll
    for (int o = 16; o > 0; o >>= 1)
        rec += __shfl_xor_sync(0xffffffffu, rec, o);

    // Smooth: fold 100 (lane,kk) accumulators into per-joint sums via smem.
    __shared__ float sj[WPB][JJ];
    if (active) sj[warp][lane] = 0.0f;
    __syncwarp();
    if (active) {
        #pragma unroll
        for (int kk = 0; kk < 4; kk++) {
            const int v = fourl + kk;
            const int j = (v >= 75) ? v - 75 : (v >= 50) ? v - 50
                        : (v >= 25) ? v - 25 : v;
            atomicAdd(&sj[warp][j], acc[kk]);
        }
    }
    __syncwarp();

    float av = (lane < JJ - 1) ? fabsf(sj[warp][lane]) : 0.0f;
    #pragma unroll
    for (int o = 16; o > 0; o >>= 1)
        av += __shfl_xor_sync(0xffffffffu, av, o);

    __shared__ double s_rec[WPB];
    __shared__ double s_sm[WPB];
    if (lane == 0) {
        s_rec[warp] = (double)rec;
        s_sm[warp]  = sqrt((double)av) / (double)TJ;
    }
    __syncthreads();

    if (threadIdx.x == 0) {
        double rtot = 0.0, stot = 0.0;
        #pragma unroll
        for (int w = 0; w < WPB; w++) { rtot += s_rec[w]; stot += s_sm[w]; }
        atomicAdd(&g_rec, rtot);
        atomicAdd(&g_smooth, stot);
        __threadfence();
        const unsigned int ticket = atomicAdd(&g_count, 1u);
        if (ticket == NBLK - 1) {
            const double rec_sum = atomicAdd(&g_rec, 0.0);
            const double sm_sum  = atomicAdd(&g_smooth, 0.0);
            const double rec_mean    = rec_sum / ((double)BB * CC * TT * JJ);
            const double smooth_mean = sm_sum  / ((double)BB * CC);
            out[0] = (float)(2.0 * rec_mean + 3.0 * smooth_mean);
            g_rec = 0.0;
            g_smooth = 0.0;
            __threadfence();
            g_count = 0u;
        }
    }
}

extern "C" void kernel_launch(void* const* d_in, const int* in_sizes, int n_in,
                              void* d_out, int out_size) {
    const float* x  = (const float*)d_in[0];
    const float* tg = (const float*)d_in[1];
    float* out = (float*)d_out;

    loss_kernel<<<NBLK, NTHREADS>>>(x, tg, out);
}